// round 2
// baseline (speedup 1.0000x reference)
#include <cuda_runtime.h>

// Soft decision tree path probabilities — barrier-free formulation.
// DEPTH=8, N_NODES=255, N_LEAVES=256, BATCH=512.
//
// Thread t (= leaf index) walks its root-to-leaf path:
//   node_d = (2^d - 1) + (t >> (8 - d)),  d = 0..7
//   bit_d  = (t >> (7 - d)) & 1   (0 -> factor x[node_d], 1 -> 1 - x[node_d])
// Running product BEFORE applying factor d equals the path prob of node_d,
// so node outputs are emitted by the leftmost leaf of each subtree
// (t with the low 8-d bits zero) — 255 writes/row total, no redundancy.
// No shared memory, no __syncthreads.
//
// Output: [ leaf_probs (512 x 256) ; node_probs (512 x 255) ] row-major.

#define ROWS_PER_BLOCK 4

__global__ __launch_bounds__(256) void tree_path_kernel(
    const float* __restrict__ x,   // (BATCH, 255)
    float* __restrict__ out,
    int batch)
{
    const int t = threadIdx.x;                 // leaf index 0..255
    float* __restrict__ out_nodes = out + (size_t)batch * 256;
    const int b0 = blockIdx.x * ROWS_PER_BLOCK;

#pragma unroll
    for (int r = 0; r < ROWS_PER_BLOCK; ++r) {
        const int b = b0 + r;
        const float* __restrict__ xr = x + (size_t)b * 255;

        // All 8 path loads are index-computable -> issue together (MLP=8).
        float xv[8];
#pragma unroll
        for (int d = 0; d < 8; ++d) {
            const int node = ((1 << d) - 1) + (t >> (8 - d));
            xv[d] = __ldg(xr + node);
        }

        float p = 1.0f;
#pragma unroll
        for (int d = 0; d < 8; ++d) {
            // p == path prob of node_d; leftmost leaf of the subtree writes it.
            if ((t & ((1 << (8 - d)) - 1)) == 0) {
                const int node = ((1 << d) - 1) + (t >> (8 - d));
                out_nodes[(size_t)b * 255 + node] = p;
            }
            const int bit = (t >> (7 - d)) & 1;
            p *= bit ? (1.0f - xv[d]) : xv[d];
        }

        out[(size_t)b * 256 + t] = p;   // leaf prob (coalesced)
    }
}

extern "C" void kernel_launch(void* const* d_in, const int* in_sizes, int n_in,
                              void* d_out, int out_size) {
    const float* x = (const float*)d_in[0];  // (BATCH, 255) float32
    float* out = (float*)d_out;
    const int batch = in_sizes[0] / 255;     // 512
    tree_path_kernel<<<batch / ROWS_PER_BLOCK, 256>>>(x, out, batch);
}

// round 3
// speedup vs baseline: 1.2546x; 1.2546x over previous
#include <cuda_runtime.h>

// Soft decision tree path probabilities.
// DEPTH=8, N_NODES=255, N_LEAVES=256, BATCH=512.
//
// Per row: stage x (coalesced) into smem, one barrier, then every thread
// (= leaf t) walks its root-to-leaf path reading 8 smem values:
//   node_d = (2^d - 1) + (t >> (8 - d)),  factor = bit ? 1-x : x
// Running product before factor d == path prob of node_d; the leftmost leaf
// of each subtree writes it (255 node writes/row, no duplication).
//
// 1024-thread CTAs process 4 rows IN PARALLEL (256 threads per row):
// full warp parallelism (512*256 threads total), 1 barrier, no level chain.
//
// Output: [ leaf_probs (512 x 256) ; node_probs (512 x 255) ] row-major.

#define ROWS_PER_BLOCK 4

__global__ __launch_bounds__(1024) void tree_path_kernel(
    const float* __restrict__ x,   // (BATCH, 255)
    float* __restrict__ out,
    int batch)
{
    __shared__ float xs[ROWS_PER_BLOCK][256];

    const int tid = threadIdx.x;
    const int r = tid >> 8;        // row slot within block (0..3)
    const int t = tid & 255;       // leaf index 0..255
    const int b = blockIdx.x * ROWS_PER_BLOCK + r;

    const float* __restrict__ xr = x + (size_t)b * 255;
    if (t < 255) xs[r][t] = xr[t];
    __syncthreads();

    float* __restrict__ out_nodes = out + (size_t)batch * 256;

    float p = 1.0f;
#pragma unroll
    for (int d = 0; d < 8; ++d) {
        const int node = ((1 << d) - 1) + (t >> (8 - d));
        // p == path prob of node_d; leftmost leaf of that subtree writes it.
        if ((t & ((1 << (8 - d)) - 1)) == 0) {
            out_nodes[(size_t)b * 255 + node] = p;
        }
        const float xv = xs[r][node];
        p *= ((t >> (7 - d)) & 1) ? (1.0f - xv) : xv;
    }

    out[(size_t)b * 256 + t] = p;  // leaf prob (coalesced)
}

extern "C" void kernel_launch(void* const* d_in, const int* in_sizes, int n_in,
                              void* d_out, int out_size) {
    const float* x = (const float*)d_in[0];  // (BATCH, 255) float32
    float* out = (float*)d_out;
    const int batch = in_sizes[0] / 255;     // 512
    tree_path_kernel<<<batch / ROWS_PER_BLOCK, 1024>>>(x, out, batch);
}